// round 6
// baseline (speedup 1.0000x reference)
#include <cuda_runtime.h>

#define NN   65536
#define EDG  524288
#define NPG  256
#define EMB  128
#define SLOPE 0.01f
#define NBLK 256

__device__ float d_cur[NN*EMB];
__device__ float d_agg[NN*64];
__device__ float d_hout[4*NN*32];
__device__ int   d_row[NN+1];
__device__ int   d_cnt[NN];
__device__ int   d_cursor[NN];
__device__ int   d_csrc[EDG];
__device__ int   d_bsum[256];
__device__ float d_cs1[3*128];
__device__ float d_cs2[3*128];
__device__ int   d_kc[12];
__device__ int   d_keptA[3*4*NN];
__device__ float d_smvA[3*NN*4];
__device__ unsigned char d_maskA[3*NN];
__device__ unsigned int d_barr;

__device__ __forceinline__ float lrelu(float v){ return v > 0.f ? v : SLOPE*v; }
__device__ __forceinline__ float neginf(){ return __int_as_float(0xff800000); }
__device__ __forceinline__ void ffma2(unsigned long long &d, unsigned long long a, unsigned long long b){
    asm("fma.rn.f32x2 %0, %1, %2, %0;" : "+l"(d) : "l"(a), "l"(b));
}

// ---------------- hist (also resets grid barrier for this call) ----------------
__global__ void k_hist(const int* __restrict__ dst){
    if (blockIdx.x == 0 && threadIdx.x == 0) d_barr = 0u;
    int e = blockIdx.x*256 + threadIdx.x;
    atomicAdd(&d_cnt[dst[e]], 1);
}

// ---------------- single-kernel scan (decoupled lookback) + zeroing ----------------
__global__ void k_scan(){
    __shared__ int s[256];
    __shared__ int pre[256];
    int t = threadIdx.x, b = blockIdx.x;
    int gid = b*256 + t;
    int v = d_cnt[gid];
    d_cnt[gid] = 0;                       // re-zero for next call
    s[t] = v; __syncthreads();
    for (int off = 1; off < 256; off <<= 1){
        int u = (t >= off) ? s[t-off] : 0;
        __syncthreads();
        s[t] += u; __syncthreads();
    }
    if (t == 0) ((volatile int*)d_bsum)[b] = s[255] + 1;   // publish (sentinel +1)
    // gather predecessor totals
    int pv = 0;
    if (t < b){
        while ((pv = ((volatile int*)d_bsum)[t]) == 0) __nanosleep(32);
        pv -= 1;
    }
    pre[t] = pv; __syncthreads();
    for (int off = 128; off; off >>= 1){
        if (t < off) pre[t] += pre[t+off];
        __syncthreads();
    }
    int r = pre[0] + s[t] - v;            // exclusive offset
    d_row[gid] = r;
    d_cursor[gid] = r;
    if (gid == NN-1) d_row[NN] = EDG;
    if (b == 0){
        if (t < 128){
            #pragma unroll
            for (int st = 0; st < 3; st++){ d_cs1[st*128+t] = 0.f; d_cs2[st*128+t] = 0.f; }
        }
        if (t < 12) d_kc[t] = 0;
    }
}

__global__ void k_fill(const int* __restrict__ src, const int* __restrict__ dst){
    if (blockIdx.x == 0) d_bsum[threadIdx.x] = 0;   // re-zero sentinels for next call
    int e = blockIdx.x*256 + threadIdx.x;
    int d = dst[e];
    int p = atomicAdd(&d_cursor[d], 1);
    d_csrc[p] = src[e];
}

// ---------------- conv0 segment-max (warp per node) ----------------
__global__ void k_agg0(const float* __restrict__ x){
    int wid  = (blockIdx.x*blockDim.x + threadIdx.x) >> 5;
    int lane = threadIdx.x & 31;
    int beg = d_row[wid], end = d_row[wid+1];
    float2 m = make_float2(neginf(), neginf());
    for (int base = beg; base < end; base += 32){
        int j = base + lane;
        int s = (j < end) ? d_csrc[j] : 0;
        int c = min(32, end - base);
        for (int t = 0; t < c; t++){
            int ss = __shfl_sync(0xffffffffu, s, t);
            float2 v = *(const float2*)(x + ss*64 + lane*2);
            m.x = fmaxf(m.x, v.x); m.y = fmaxf(m.y, v.y);
        }
    }
    if (m.x == neginf()) m.x = 0.f;
    if (m.y == neginf()) m.y = 0.f;
    *(float2*)(d_agg + wid*64 + lane*2) = m;
}

// ---------------- conv0 GEMM (128x128 tile, 8x8/thread, FFMA2) ----------------
#define GSMEM (2*128*132*4 + 256*4)
__global__ void __launch_bounds__(256,1) k_gemm0(const float* __restrict__ Wrel,
        const float* __restrict__ Wroot, const float* __restrict__ bias,
        const float* __restrict__ x){
    extern __shared__ float smp[];
    float* As  = smp;
    float* Ws  = smp + 128*132;
    float* sc1 = smp + 2*128*132;
    float* sc2 = sc1 + 128;
    int tid = threadIdx.x;
    int row0 = blockIdx.x*128;
    for (int idx = tid; idx < 128*128; idx += 256){
        int r = idx >> 7, c = idx & 127;
        As[r*132+c] = (c < 64) ? d_agg[(row0+r)*64 + c] : x[(row0+r)*64 + (c-64)];
        Ws[r*132+c] = (c < 64) ? Wrel[r*64 + c] : Wroot[r*64 + (c-64)];
    }
    if (tid < 128){ sc1[tid] = 0.f; sc2[tid] = 0.f; }
    __syncthreads();
    int tx = tid & 15, ty = tid >> 4;
    unsigned long long acc[8][8];
    #pragma unroll
    for (int r = 0; r < 8; r++)
        #pragma unroll
        for (int c = 0; c < 8; c++) acc[r][c] = 0ull;
    int ra = ty*4, rb = 64 + ty*4;
    for (int k = 0; k < 128; k += 4){
        ulonglong2 a[8];
        #pragma unroll
        for (int r = 0; r < 4; r++){
            a[r]   = *(const ulonglong2*)(As + (ra+r)*132 + k);
            a[r+4] = *(const ulonglong2*)(As + (rb+r)*132 + k);
        }
        #pragma unroll
        for (int cc = 0; cc < 8; cc++){
            ulonglong2 w = *(const ulonglong2*)(Ws + (cc*16+tx)*132 + k);
            #pragma unroll
            for (int r = 0; r < 8; r++){
                ffma2(acc[r][cc], a[r].x, w.x);
                ffma2(acc[r][cc], a[r].y, w.y);
            }
        }
    }
    #pragma unroll
    for (int cc = 0; cc < 8; cc++){
        int col = cc*16 + tx;
        float b = __ldg(&bias[col]);
        float a1 = 0.f, a2 = 0.f;
        #pragma unroll
        for (int r = 0; r < 8; r++){
            float2 f = *(float2*)&acc[r][cc];
            float h = f.x + f.y + b;
            h = (h > 0.f) ? h : SLOPE*h;
            int row = row0 + ((r < 4) ? (ra+r) : (rb+r-4));
            d_cur[row*EMB + col] = h;
            a1 += h; a2 += h*h;
        }
        atomicAdd(&sc1[col], a1);
        atomicAdd(&sc2[col], a2);
    }
    __syncthreads();
    if (tid < 128){
        atomicAdd(&d_cs1[tid], sc1[tid]);
        atomicAdd(&d_cs2[tid], sc2[tid]);
    }
}

// ================= persistent mega kernel =================
__device__ __forceinline__ void gridbar(unsigned int target){
    __syncthreads();
    if (threadIdx.x == 0){
        __threadfence();
        atomicAdd(&d_barr, 1u);
        while (*(volatile unsigned int*)&d_barr < target) __nanosleep(64);
        __threadfence();
    }
    __syncthreads();
}

__device__ void stage_phase(int stage, const float* __restrict__ bng, const float* __restrict__ bnb,
                            const float* __restrict__ w4, float min_score, int mode){
    __shared__ float sscale[128], sshift[128], scorr[128], sw[512];
    __shared__ float4 red[256];
    __shared__ float sm4[4], ssum[4], sthr[4];
    int t = threadIdx.x;
    if (t < 128){
        float c1 = __ldcg(&d_cs1[stage*128 + t]);
        float c2 = __ldcg(&d_cs2[stage*128 + t]);
        float mu  = c1 * (1.f/NN);
        float var = c2 * (1.f/NN) - mu*mu;
        float r   = rsqrtf(var + 1e-5f);
        float gr  = bng[t]*r;
        if (mode == 0){ sscale[t] = gr;   sshift[t] = bnb[t] - gr*mu;          scorr[t] = 0.f; }
        else          { sscale[t] = 0.5f; sshift[t] = 0.25f*(bnb[t] - gr*mu);  scorr[t] = 0.25f*gr; }
    }
    sw[t] = w4[t]; sw[t+256] = w4[t+256];
    __syncthreads();
    int n = blockIdx.x*NPG + t;
    unsigned char pm = mode ? d_maskA[(stage-1)*NN + n] : (unsigned char)0;
    float* cur = d_cur + n*EMB;
    float s0 = 0.f, s1 = 0.f, s2 = 0.f, s3 = 0.f;
    for (int c4 = 0; c4 < 128; c4 += 4){
        float4 v  = *(float4*)(cur + c4);
        float4 scv = *(float4*)(sscale + c4);
        float4 shv = *(float4*)(sshift + c4);
        v.x = scv.x*v.x + shv.x; v.y = scv.y*v.y + shv.y;
        v.z = scv.z*v.z + shv.z; v.w = scv.w*v.w + shv.w;
        int hd = c4 >> 5;
        if (pm & (1u << hd)){
            float4 o  = __ldcg((const float4*)(d_hout + ((hd*NN + n)*32) + (c4 & 31)));
            float4 cr = *(float4*)(scorr + c4);
            v.x += cr.x*o.x; v.y += cr.y*o.y; v.z += cr.z*o.z; v.w += cr.w*o.w;
        }
        *(float4*)(cur + c4) = v;
        s0 += v.x*sw[c4] + v.y*sw[c4+1] + v.z*sw[c4+2] + v.w*sw[c4+3];
        s1 += v.x*sw[128+c4] + v.y*sw[128+c4+1] + v.z*sw[128+c4+2] + v.w*sw[128+c4+3];
        s2 += v.x*sw[256+c4] + v.y*sw[256+c4+1] + v.z*sw[256+c4+2] + v.w*sw[256+c4+3];
        s3 += v.x*sw[384+c4] + v.y*sw[384+c4+1] + v.z*sw[384+c4+2] + v.w*sw[384+c4+3];
    }
    red[t] = make_float4(s0, s1, s2, s3); __syncthreads();
    for (int off = 128; off; off >>= 1){
        if (t < off){
            float4 a = red[t], b = red[t+off];
            red[t] = make_float4(fmaxf(a.x,b.x), fmaxf(a.y,b.y), fmaxf(a.z,b.z), fmaxf(a.w,b.w));
        }
        __syncthreads();
    }
    if (t == 0){ float4 mm = red[0]; sm4[0]=mm.x; sm4[1]=mm.y; sm4[2]=mm.z; sm4[3]=mm.w; }
    __syncthreads();
    float4 e = make_float4(expf(s0-sm4[0]), expf(s1-sm4[1]), expf(s2-sm4[2]), expf(s3-sm4[3]));
    red[t] = e; __syncthreads();
    for (int off = 128; off; off >>= 1){
        if (t < off){
            float4 a = red[t], b = red[t+off];
            red[t] = make_float4(a.x+b.x, a.y+b.y, a.z+b.z, a.w+b.w);
        }
        __syncthreads();
    }
    if (t == 0){ float4 ss = red[0]; ssum[0]=ss.x; ssum[1]=ss.y; ssum[2]=ss.z; ssum[3]=ss.w; }
    __syncthreads();
    if (t < 4) sthr[t] = fminf(1.f/(ssum[t] + 1e-16f) - 1e-7f, min_score);
    __syncthreads();
    float sv0 = e.x/(ssum[0]+1e-16f), sv1 = e.y/(ssum[1]+1e-16f);
    float sv2 = e.z/(ssum[2]+1e-16f), sv3 = e.w/(ssum[3]+1e-16f);
    int* kc = d_kc + stage*4;
    int* kept = d_keptA + stage*4*NN;
    unsigned char mk = 0;
    if (sv0 > sthr[0]){ mk |= 1; kept[0*NN + atomicAdd(kc+0,1)] = n; }
    if (sv1 > sthr[1]){ mk |= 2; kept[1*NN + atomicAdd(kc+1,1)] = n; }
    if (sv2 > sthr[2]){ mk |= 4; kept[2*NN + atomicAdd(kc+2,1)] = n; }
    if (sv3 > sthr[3]){ mk |= 8; kept[3*NN + atomicAdd(kc+3,1)] = n; }
    *(float4*)(d_smvA + (stage*NN + n)*4) = make_float4(sv0, sv1, sv2, sv3);
    d_maskA[stage*NN + n] = mk;
}

__device__ void headconv_phase(int stage, const float* __restrict__ Wrel,
                               const float* __restrict__ Wroot, const float* __restrict__ bias){
    __shared__ float hax[128], hxs[128], hred[256];
    int t = threadIdx.x;
    int oc = t & 31, q = t >> 5;
    const unsigned char* mv = d_maskA + stage*NN;
    const float* sv = d_smvA + stage*NN*4;
    float* cs1 = d_cs1 + (stage+1)*128;
    float* cs2 = d_cs2 + (stage+1)*128;
    #pragma unroll 1
    for (int h = 0; h < 4; h++){
        int nk = d_kc[stage*4 + h];
        unsigned char bit = (unsigned char)(1 << h);
        const int* kept = d_keptA + (stage*4 + h)*NN;
        for (int slot = blockIdx.x; slot < nk; slot += NBLK){
            int i = kept[slot];
            if (t < 128){
                float m = neginf();
                int beg = d_row[i], end = d_row[i+1];
                for (int j = beg; j < end; j++){
                    int s = d_csrc[j];
                    if (__ldcg(&mv[s]) & bit)
                        m = fmaxf(m, __ldcg(&d_cur[s*EMB + t]) * __ldcg(&sv[s*4 + h]));
                }
                hax[t] = (m == neginf()) ? 0.f : m;
                hxs[t] = __ldcg(&d_cur[i*EMB + t]) * __ldcg(&sv[i*4 + h]);
            }
            __syncthreads();
            {
                const float* wr = Wrel  + (h*32 + oc)*EMB + q*16;
                const float* wt = Wroot + (h*32 + oc)*EMB + q*16;
                float acc = 0.f;
                #pragma unroll
                for (int k = 0; k < 16; k++) acc += hax[q*16+k]*wr[k] + hxs[q*16+k]*wt[k];
                hred[t] = acc;
            }
            __syncthreads();
            if (q == 0){
                float o = bias[h*32 + oc];
                #pragma unroll
                for (int p = 0; p < 8; p++) o += hred[p*32 + oc];
                o = lrelu(o);
                d_hout[(h*NN + i)*32 + oc] = o;
                atomicAdd(&cs1[h*32 + oc], o);
                atomicAdd(&cs2[h*32 + oc], o*o);
            }
            __syncthreads();
        }
    }
}

__device__ void cls_phase(const float* __restrict__ gW1, const float* __restrict__ gb1,
                          const float* __restrict__ gW2, const float* __restrict__ gb2,
                          const float* __restrict__ fW1, const float* __restrict__ fb1,
                          const float* __restrict__ fW2, const float* __restrict__ fb2,
                          float* __restrict__ out){
    __shared__ float cxp[128], cpool[128], cred[128], cgates[16], cslog[4];
    __shared__ int cknod[16], ckn;
    int g = blockIdx.x, t = threadIdx.x;
    const unsigned char* mv = d_maskA + 2*NN;
    const float* sv = d_smvA + 2*NN*4;
    #pragma unroll 1
    for (int c = 0; c < 4; c++){
        if (t == 0) ckn = 0;
        __syncthreads();
        {
            int n = g*NPG + t;
            if ((mv[n] >> c) & 1){
                int idx = atomicAdd(&ckn, 1);
                if (idx < 16) cknod[idx] = n;
            }
        }
        __syncthreads();
        int K = min(ckn, 16);
        for (int ki = 0; ki < K; ki++){
            int i = cknod[ki];
            if (t < 128) cxp[t] = d_cur[i*EMB + t] * sv[i*4 + c];
            __syncthreads();
            if (t < 128){
                const float* w = gW1 + (c*128 + t)*128;
                float acc = gb1[c*128 + t];
                #pragma unroll 8
                for (int k = 0; k < 128; k++) acc += cxp[k]*w[k];
                cred[t] = lrelu(acc) * gW2[c*128 + t];
            }
            __syncthreads();
            for (int off = 64; off; off >>= 1){
                if (t < off) cred[t] += cred[t+off];
                __syncthreads();
            }
            if (t == 0) cgates[ki] = cred[0] + gb2[c];
            __syncthreads();
        }
        float m = neginf();
        for (int ki = 0; ki < K; ki++) m = fmaxf(m, cgates[ki]);
        float s = 0.f;
        for (int ki = 0; ki < K; ki++) s += expf(cgates[ki] - m);
        float inv = 1.f/(s + 1e-16f);
        if (t < 128){
            float p = 0.f;
            for (int ki = 0; ki < K; ki++){
                int i = cknod[ki];
                float aw = expf(cgates[ki] - m) * inv * sv[i*4 + c];
                p += aw * d_cur[i*EMB + t];
            }
            cpool[t] = p;
        }
        __syncthreads();
        if (t < 128){
            const float* w = fW1 + (c*128 + t)*128;
            float acc = fb1[c*128 + t];
            #pragma unroll 8
            for (int k = 0; k < 128; k++) acc += cpool[k]*w[k];
            cred[t] = lrelu(acc) * fW2[c*128 + t];
        }
        __syncthreads();
        for (int off = 64; off; off >>= 1){
            if (t < off) cred[t] += cred[t+off];
            __syncthreads();
        }
        if (t == 0) cslog[c] = cred[0] + fb2[c];
        __syncthreads();
    }
    if (t == 0){
        float z0 = cslog[0], z1 = cslog[1], z2 = cslog[2], z3 = cslog[3];
        float m = fmaxf(fmaxf(z0,z1), fmaxf(z2,z3));
        float l = logf(expf(z0-m) + expf(z1-m) + expf(z2-m) + expf(z3-m));
        out[g*4+0] = z0 - m - l;
        out[g*4+1] = z1 - m - l;
        out[g*4+2] = z2 - m - l;
        out[g*4+3] = z3 - m - l;
    }
}

__global__ void __launch_bounds__(256,2) k_mega(
        const float* __restrict__ bn0g, const float* __restrict__ bn0b,
        const float* __restrict__ bpw,
        const float* __restrict__ bWrel, const float* __restrict__ bWroot,
        const float* __restrict__ bb,
        const float* __restrict__ bbng, const float* __restrict__ bbnb,
        const float* __restrict__ cpw,
        const float* __restrict__ gW1, const float* __restrict__ gb1,
        const float* __restrict__ gW2, const float* __restrict__ gb2,
        const float* __restrict__ fW1, const float* __restrict__ fb1,
        const float* __restrict__ fW2, const float* __restrict__ fb2,
        float* __restrict__ out){
    stage_phase(0, bn0g, bn0b, bpw + 0*512, 0.7f, 0);
    gridbar(1*NBLK);
    headconv_phase(0, bWrel, bWroot, bb);
    gridbar(2*NBLK);
    stage_phase(1, bbng, bbnb, bpw + 1*512, 0.7f, 1);
    gridbar(3*NBLK);
    headconv_phase(1, bWrel + 4*32*EMB, bWroot + 4*32*EMB, bb + 128);
    gridbar(4*NBLK);
    stage_phase(2, bbng + EMB, bbnb + EMB, cpw, 0.8f, 1);
    gridbar(5*NBLK);
    cls_phase(gW1, gb1, gW2, gb2, fW1, fb1, fW2, fb2, out);
}

extern "C" void kernel_launch(void* const* d_in, const int* in_sizes, int n_in,
                              void* d_out, int out_size){
    (void)in_sizes; (void)n_in; (void)out_size;
    const float* x      = (const float*)d_in[0];
    const int*   ei     = (const int*)  d_in[1];
    const int*   src    = ei;
    const int*   dst    = ei + EDG;
    const float* Wrel0  = (const float*)d_in[3];
    const float* Wroot0 = (const float*)d_in[4];
    const float* b0     = (const float*)d_in[5];
    const float* bn0g   = (const float*)d_in[6];
    const float* bn0b   = (const float*)d_in[7];
    const float* bpw    = (const float*)d_in[8];
    const float* bWrel  = (const float*)d_in[9];
    const float* bWroot = (const float*)d_in[10];
    const float* bb     = (const float*)d_in[11];
    const float* bbng   = (const float*)d_in[12];
    const float* bbnb   = (const float*)d_in[13];
    const float* cpw    = (const float*)d_in[14];
    const float* gW1    = (const float*)d_in[15];
    const float* gb1    = (const float*)d_in[16];
    const float* gW2    = (const float*)d_in[17];
    const float* gb2    = (const float*)d_in[18];
    const float* fW1    = (const float*)d_in[19];
    const float* fb1    = (const float*)d_in[20];
    const float* fW2    = (const float*)d_in[21];
    const float* fb2    = (const float*)d_in[22];
    float* out = (float*)d_out;

    cudaFuncSetAttribute(k_gemm0, cudaFuncAttributeMaxDynamicSharedMemorySize, GSMEM);

    k_hist<<<EDG/256, 256>>>(dst);                 // launch 0
    k_scan<<<256, 256>>>();                        // launch 1
    k_fill<<<EDG/256, 256>>>(src, dst);            // launch 2
    k_agg0<<<NN/8, 256>>>(x);                      // launch 3  <- ncu capture lands here
    k_gemm0<<<NN/128, 256, GSMEM>>>(Wrel0, Wroot0, b0, x);   // launch 4
    k_mega<<<NBLK, 256>>>(bn0g, bn0b, bpw, bWrel, bWroot, bb, bbng, bbnb,
                          cpw, gW1, gb1, gW2, gb2, fW1, fb1, fW2, fb2, out);  // launch 5
}

// round 9
// speedup vs baseline: 1.0299x; 1.0299x over previous
#include <cuda_runtime.h>

#define NN   65536
#define EDG  524288
#define NPG  256
#define EMB  128
#define SLOPE 0.01f
#define NBLK 256

__device__ float d_cur[NN*EMB];
__device__ float d_agg[NN*64];
__device__ float d_hout[4*NN*32];
__device__ int   d_row[NN+1];
__device__ int   d_cnt[NN];
__device__ int   d_cursor[NN];
__device__ int   d_csrc[EDG];
__device__ int   d_bsum[256];
__device__ float d_cs1[3*128];
__device__ float d_cs2[3*128];
__device__ int   d_kc[12];
__device__ int   d_keptA[3*4*NN];
__device__ float d_smvA[3*NN*4];
__device__ unsigned char d_maskA[3*NN];
__device__ unsigned int d_barrA;
__device__ unsigned int d_barrB;

__device__ __forceinline__ float lrelu(float v){ return v > 0.f ? v : SLOPE*v; }
__device__ __forceinline__ float neginf(){ return __int_as_float(0xff800000); }
__device__ __forceinline__ void ffma2(unsigned long long &d, unsigned long long a, unsigned long long b){
    asm("fma.rn.f32x2 %0, %1, %2, %0;" : "+l"(d) : "l"(a), "l"(b));
}

__device__ __forceinline__ void gbar(unsigned int* ctr, unsigned int target){
    __syncthreads();
    if (threadIdx.x == 0){
        __threadfence();
        atomicAdd(ctr, 1u);
        while (*(volatile unsigned int*)ctr < target) __nanosleep(64);
        __threadfence();
    }
    __syncthreads();
}

// ================= CSR build: hist + scan + fill in ONE persistent kernel =================
__global__ void __launch_bounds__(256,2) k_csr(const int* __restrict__ src, const int* __restrict__ dst){
    __shared__ int s[256];
    __shared__ int pre[256];
    int t = threadIdx.x, b = blockIdx.x;
    if (b == 0 && t == 0) d_barrB = 0u;       // reset mega's barrier for this call
    int e0 = b*2048;
    // phase 0: histogram (d_cnt zeroed by previous call / static init)
    #pragma unroll
    for (int i = 0; i < 8; i++){
        int e = e0 + i*256 + t;
        atomicAdd(&d_cnt[dst[e]], 1);
    }
    gbar(&d_barrA, 1*NBLK);
    // phase 1: per-block inclusive scan of its 256 counters
    int gid = b*256 + t;
    int v = __ldcg(&d_cnt[gid]);
    d_cnt[gid] = 0;                            // re-zero for next call
    s[t] = v; __syncthreads();
    for (int off = 1; off < 256; off <<= 1){
        int u = (t >= off) ? s[t-off] : 0;
        __syncthreads();
        s[t] += u; __syncthreads();
    }
    d_row[gid] = s[t] - v;                     // local exclusive (temp)
    if (t == 255) d_bsum[b] = s[255];
    gbar(&d_barrA, 2*NBLK);
    // phase 2: global offset + cursor init (+ zero stats on block 0)
    pre[t] = (t < b) ? __ldcg(&d_bsum[t]) : 0;
    __syncthreads();
    for (int off = 128; off; off >>= 1){
        if (t < off) pre[t] += pre[t+off];
        __syncthreads();
    }
    int r = pre[0] + d_row[gid];
    d_row[gid] = r;
    d_cursor[gid] = r;
    if (gid == NN-1) d_row[NN] = EDG;
    if (b == 0){
        if (t < 128){
            #pragma unroll
            for (int st = 0; st < 3; st++){ d_cs1[st*128+t] = 0.f; d_cs2[st*128+t] = 0.f; }
        }
        if (t < 12) d_kc[t] = 0;
    }
    gbar(&d_barrA, 3*NBLK);
    // phase 3: fill
    #pragma unroll
    for (int i = 0; i < 8; i++){
        int e = e0 + i*256 + t;
        int d = dst[e];
        int p = atomicAdd(&d_cursor[d], 1);
        d_csrc[p] = src[e];
    }
}

// ---------------- conv0 segment-max (warp per node) ----------------
__global__ void k_agg0(const float* __restrict__ x){
    int wid  = (blockIdx.x*blockDim.x + threadIdx.x) >> 5;
    int lane = threadIdx.x & 31;
    int beg = d_row[wid], end = d_row[wid+1];
    float2 m = make_float2(neginf(), neginf());
    for (int base = beg; base < end; base += 32){
        int j = base + lane;
        int s = (j < end) ? d_csrc[j] : 0;
        int c = min(32, end - base);
        for (int t = 0; t < c; t++){
            int ss = __shfl_sync(0xffffffffu, s, t);
            float2 v = *(const float2*)(x + ss*64 + lane*2);
            m.x = fmaxf(m.x, v.x); m.y = fmaxf(m.y, v.y);
        }
    }
    if (m.x == neginf()) m.x = 0.f;
    if (m.y == neginf()) m.y = 0.f;
    *(float2*)(d_agg + wid*64 + lane*2) = m;
}

// ---------------- conv0 GEMM (128x128 tile, 8x8/thread, FFMA2) ----------------
#define GSMEM (2*128*132*4 + 256*4)
__global__ void __launch_bounds__(256,1) k_gemm0(const float* __restrict__ Wrel,
        const float* __restrict__ Wroot, const float* __restrict__ bias,
        const float* __restrict__ x){
    extern __shared__ float smp[];
    float* As  = smp;
    float* Ws  = smp + 128*132;
    float* sc1 = smp + 2*128*132;
    float* sc2 = sc1 + 128;
    int tid = threadIdx.x;
    int row0 = blockIdx.x*128;
    for (int idx = tid; idx < 128*128; idx += 256){
        int r = idx >> 7, c = idx & 127;
        As[r*132+c] = (c < 64) ? d_agg[(row0+r)*64 + c] : x[(row0+r)*64 + (c-64)];
        Ws[r*132+c] = (c < 64) ? Wrel[r*64 + c] : Wroot[r*64 + (c-64)];
    }
    if (tid < 128){ sc1[tid] = 0.f; sc2[tid] = 0.f; }
    __syncthreads();
    int tx = tid & 15, ty = tid >> 4;
    unsigned long long acc[8][8];
    #pragma unroll
    for (int r = 0; r < 8; r++)
        #pragma unroll
        for (int c = 0; c < 8; c++) acc[r][c] = 0ull;
    int ra = ty*4, rb = 64 + ty*4;
    for (int k = 0; k < 128; k += 4){
        ulonglong2 a[8];
        #pragma unroll
        for (int r = 0; r < 4; r++){
            a[r]   = *(const ulonglong2*)(As + (ra+r)*132 + k);
            a[r+4] = *(const ulonglong2*)(As + (rb+r)*132 + k);
        }
        #pragma unroll
        for (int cc = 0; cc < 8; cc++){
            ulonglong2 w = *(const ulonglong2*)(Ws + (cc*16+tx)*132 + k);
            #pragma unroll
            for (int r = 0; r < 8; r++){
                ffma2(acc[r][cc], a[r].x, w.x);
                ffma2(acc[r][cc], a[r].y, w.y);
            }
        }
    }
    #pragma unroll
    for (int cc = 0; cc < 8; cc++){
        int col = cc*16 + tx;
        float b = __ldg(&bias[col]);
        float a1 = 0.f, a2 = 0.f;
        #pragma unroll
        for (int r = 0; r < 8; r++){
            float2 f = *(float2*)&acc[r][cc];
            float h = f.x + f.y + b;
            h = (h > 0.f) ? h : SLOPE*h;
            int row = row0 + ((r < 4) ? (ra+r) : (rb+r-4));
            d_cur[row*EMB + col] = h;
            a1 += h; a2 += h*h;
        }
        atomicAdd(&sc1[col], a1);
        atomicAdd(&sc2[col], a2);
    }
    __syncthreads();
    if (tid < 128){
        atomicAdd(&d_cs1[tid], sc1[tid]);
        atomicAdd(&d_cs2[tid], sc2[tid]);
    }
}

// ================= persistent mega kernel =================
__device__ void stage_phase(int stage, const float* __restrict__ bng, const float* __restrict__ bnb,
                            const float* __restrict__ w4, float min_score, int mode){
    __shared__ float sscale[128], sshift[128], scorr[128], sw[512];
    __shared__ float sc0[256], sc1v[256], sc2v[256], sc3v[256];
    __shared__ float4 red[256];
    __shared__ float sm4[4], ssum[4], sthr[4];
    int t = threadIdx.x, g = blockIdx.x;
    if (t < 128){
        float c1 = __ldcg(&d_cs1[stage*128 + t]);
        float c2 = __ldcg(&d_cs2[stage*128 + t]);
        float mu  = c1 * (1.f/NN);
        float var = c2 * (1.f/NN) - mu*mu;
        float r   = rsqrtf(var + 1e-5f);
        float gr  = bng[t]*r;
        if (mode == 0){ sscale[t] = gr;   sshift[t] = bnb[t] - gr*mu;          scorr[t] = 0.f; }
        else          { sscale[t] = 0.5f; sshift[t] = 0.25f*(bnb[t] - gr*mu);  scorr[t] = 0.25f*gr; }
    }
    sw[t] = w4[t]; sw[t+256] = w4[t+256];
    __syncthreads();
    int w = t >> 5, lane = t & 31;
    int hd = lane >> 3;
    float4 scv = *(float4*)(sscale + lane*4);
    float4 shv = *(float4*)(sshift + lane*4);
    float4 crv = *(float4*)(scorr + lane*4);
    float4 wv0 = *(float4*)(sw + lane*4);
    float4 wv1 = *(float4*)(sw + 128 + lane*4);
    float4 wv2 = *(float4*)(sw + 256 + lane*4);
    float4 wv3 = *(float4*)(sw + 384 + lane*4);
    const unsigned char* pmv = d_maskA + (stage > 0 ? (stage-1) : 0)*NN;
    #pragma unroll 1
    for (int it = 0; it < 32; it++){
        int idx = it*8 + w;
        int n = g*NPG + idx;
        float4 v = *(float4*)(d_cur + n*EMB + lane*4);
        v.x = scv.x*v.x + shv.x; v.y = scv.y*v.y + shv.y;
        v.z = scv.z*v.z + shv.z; v.w = scv.w*v.w + shv.w;
        if (mode){
            unsigned char pm = __ldcg(&pmv[n]);
            if ((pm >> hd) & 1){
                float4 o = __ldcg((const float4*)(d_hout + (hd*NN + n)*32 + (lane & 7)*4));
                v.x += crv.x*o.x; v.y += crv.y*o.y; v.z += crv.z*o.z; v.w += crv.w*o.w;
            }
        }
        *(float4*)(d_cur + n*EMB + lane*4) = v;
        float p0 = v.x*wv0.x + v.y*wv0.y + v.z*wv0.z + v.w*wv0.w;
        float p1 = v.x*wv1.x + v.y*wv1.y + v.z*wv1.z + v.w*wv1.w;
        float p2 = v.x*wv2.x + v.y*wv2.y + v.z*wv2.z + v.w*wv2.w;
        float p3 = v.x*wv3.x + v.y*wv3.y + v.z*wv3.z + v.w*wv3.w;
        #pragma unroll
        for (int off = 16; off; off >>= 1){
            p0 += __shfl_xor_sync(0xffffffffu, p0, off);
            p1 += __shfl_xor_sync(0xffffffffu, p1, off);
            p2 += __shfl_xor_sync(0xffffffffu, p2, off);
            p3 += __shfl_xor_sync(0xffffffffu, p3, off);
        }
        if (lane == 0){ sc0[idx] = p0; sc1v[idx] = p1; sc2v[idx] = p2; sc3v[idx] = p3; }
    }
    __syncthreads();
    float4 z = make_float4(sc0[t], sc1v[t], sc2v[t], sc3v[t]);
    red[t] = z; __syncthreads();
    for (int off = 128; off; off >>= 1){
        if (t < off){
            float4 a = red[t], b = red[t+off];
            red[t] = make_float4(fmaxf(a.x,b.x), fmaxf(a.y,b.y), fmaxf(a.z,b.z), fmaxf(a.w,b.w));
        }
        __syncthreads();
    }
    if (t == 0){ float4 mm = red[0]; sm4[0]=mm.x; sm4[1]=mm.y; sm4[2]=mm.z; sm4[3]=mm.w; }
    __syncthreads();
    float4 e = make_float4(expf(z.x-sm4[0]), expf(z.y-sm4[1]), expf(z.z-sm4[2]), expf(z.w-sm4[3]));
    red[t] = e; __syncthreads();
    for (int off = 128; off; off >>= 1){
        if (t < off){
            float4 a = red[t], b = red[t+off];
            red[t] = make_float4(a.x+b.x, a.y+b.y, a.z+b.z, a.w+b.w);
        }
        __syncthreads();
    }
    if (t == 0){ float4 ss = red[0]; ssum[0]=ss.x; ssum[1]=ss.y; ssum[2]=ss.z; ssum[3]=ss.w; }
    __syncthreads();
    if (t < 4) sthr[t] = fminf(1.f/(ssum[t] + 1e-16f) - 1e-7f, min_score);
    __syncthreads();
    int n = g*NPG + t;
    float sv0 = e.x/(ssum[0]+1e-16f), sv1 = e.y/(ssum[1]+1e-16f);
    float sv2 = e.z/(ssum[2]+1e-16f), sv3 = e.w/(ssum[3]+1e-16f);
    int* kc = d_kc + stage*4;
    int* kept = d_keptA + stage*4*NN;
    unsigned char mk = 0;
    if (sv0 > sthr[0]){ mk |= 1; kept[0*NN + atomicAdd(kc+0,1)] = n; }
    if (sv1 > sthr[1]){ mk |= 2; kept[1*NN + atomicAdd(kc+1,1)] = n; }
    if (sv2 > sthr[2]){ mk |= 4; kept[2*NN + atomicAdd(kc+2,1)] = n; }
    if (sv3 > sthr[3]){ mk |= 8; kept[3*NN + atomicAdd(kc+3,1)] = n; }
    *(float4*)(d_smvA + (stage*NN + n)*4) = make_float4(sv0, sv1, sv2, sv3);
    d_maskA[stage*NN + n] = mk;
}

__device__ void headconv_phase(int stage, const float* __restrict__ Wrel,
                               const float* __restrict__ Wroot, const float* __restrict__ bias){
    __shared__ float hax[128], hxs[128], hred[256];
    int t = threadIdx.x;
    int oc = t & 31, q = t >> 5;
    const unsigned char* mv = d_maskA + stage*NN;
    const float* sv = d_smvA + stage*NN*4;
    float* cs1 = d_cs1 + (stage+1)*128;
    float* cs2 = d_cs2 + (stage+1)*128;
    #pragma unroll 1
    for (int h = 0; h < 4; h++){
        int nk = __ldcg(&d_kc[stage*4 + h]);
        unsigned char bit = (unsigned char)(1 << h);
        const int* kept = d_keptA + (stage*4 + h)*NN;
        for (int slot = blockIdx.x; slot < nk; slot += NBLK){
            int i = __ldcg(&kept[slot]);
            if (t < 128){
                float m = neginf();
                int beg = d_row[i], end = d_row[i+1];
                for (int j = beg; j < end; j++){
                    int s = d_csrc[j];
                    if (__ldcg(&mv[s]) & bit)
                        m = fmaxf(m, __ldcg(&d_cur[s*EMB + t]) * __ldcg(&sv[s*4 + h]));
                }
                hax[t] = (m == neginf()) ? 0.f : m;
                hxs[t] = __ldcg(&d_cur[i*EMB + t]) * __ldcg(&sv[i*4 + h]);
            }
            __syncthreads();
            {
                const float* wr = Wrel  + (h*32 + oc)*EMB + q*16;
                const float* wt = Wroot + (h*32 + oc)*EMB + q*16;
                float acc = 0.f;
                #pragma unroll
                for (int k = 0; k < 16; k++) acc += hax[q*16+k]*wr[k] + hxs[q*16+k]*wt[k];
                hred[t] = acc;
            }
            __syncthreads();
            if (q == 0){
                float o = bias[h*32 + oc];
                #pragma unroll
                for (int p = 0; p < 8; p++) o += hred[p*32 + oc];
                o = lrelu(o);
                d_hout[(h*NN + i)*32 + oc] = o;
                atomicAdd(&cs1[h*32 + oc], o);
                atomicAdd(&cs2[h*32 + oc], o*o);
            }
            __syncthreads();
        }
    }
}

__device__ void cls_phase(const float* __restrict__ gW1, const float* __restrict__ gb1,
                          const float* __restrict__ gW2, const float* __restrict__ gb2,
                          const float* __restrict__ fW1, const float* __restrict__ fb1,
                          const float* __restrict__ fW2, const float* __restrict__ fb2,
                          float* __restrict__ out){
    __shared__ float cxp[128], cpool[128], cred[128], cgates[16], cslog[4];
    __shared__ int cknod[16], ckn;
    int g = blockIdx.x, t = threadIdx.x;
    const unsigned char* mv = d_maskA + 2*NN;
    const float* sv = d_smvA + 2*NN*4;
    #pragma unroll 1
    for (int c = 0; c < 4; c++){
        if (t == 0) ckn = 0;
        __syncthreads();
        {
            int n = g*NPG + t;
            if ((mv[n] >> c) & 1){
                int idx = atomicAdd(&ckn, 1);
                if (idx < 16) cknod[idx] = n;
            }
        }
        __syncthreads();
        int K = min(ckn, 16);
        for (int ki = 0; ki < K; ki++){
            int i = cknod[ki];
            if (t < 128) cxp[t] = d_cur[i*EMB + t] * sv[i*4 + c];
            __syncthreads();
            if (t < 128){
                const float* w = gW1 + (c*128 + t)*128;
                float acc = gb1[c*128 + t];
                #pragma unroll 8
                for (int k = 0; k < 128; k++) acc += cxp[k]*w[k];
                cred[t] = lrelu(acc) * gW2[c*128 + t];
            }
            __syncthreads();
            for (int off = 64; off; off >>= 1){
                if (t < off) cred[t] += cred[t+off];
                __syncthreads();
            }
            if (t == 0) cgates[ki] = cred[0] + gb2[c];
            __syncthreads();
        }
        float m = neginf();
        for (int ki = 0; ki < K; ki++) m = fmaxf(m, cgates[ki]);
        float s = 0.f;
        for (int ki = 0; ki < K; ki++) s += expf(cgates[ki] - m);
        float inv = 1.f/(s + 1e-16f);
        if (t < 128){
            float p = 0.f;
            for (int ki = 0; ki < K; ki++){
                int i = cknod[ki];
                float aw = expf(cgates[ki] - m) * inv * sv[i*4 + c];
                p += aw * d_cur[i*EMB + t];
            }
            cpool[t] = p;
        }
        __syncthreads();
        if (t < 128){
            const float* w = fW1 + (c*128 + t)*128;
            float acc = fb1[c*128 + t];
            #pragma unroll 8
            for (int k = 0; k < 128; k++) acc += cpool[k]*w[k];
            cred[t] = lrelu(acc) * fW2[c*128 + t];
        }
        __syncthreads();
        for (int off = 64; off; off >>= 1){
            if (t < off) cred[t] += cred[t+off];
            __syncthreads();
        }
        if (t == 0) cslog[c] = cred[0] + fb2[c];
        __syncthreads();
    }
    if (t == 0){
        float z0 = cslog[0], z1 = cslog[1], z2 = cslog[2], z3 = cslog[3];
        float m = fmaxf(fmaxf(z0,z1), fmaxf(z2,z3));
        float l = logf(expf(z0-m) + expf(z1-m) + expf(z2-m) + expf(z3-m));
        out[g*4+0] = z0 - m - l;
        out[g*4+1] = z1 - m - l;
        out[g*4+2] = z2 - m - l;
        out[g*4+3] = z3 - m - l;
    }
}

__global__ void __launch_bounds__(256,2) k_mega(
        const float* __restrict__ bn0g, const float* __restrict__ bn0b,
        const float* __restrict__ bpw,
        const float* __restrict__ bWrel, const float* __restrict__ bWroot,
        const float* __restrict__ bb,
        const float* __restrict__ bbng, const float* __restrict__ bbnb,
        const float* __restrict__ cpw,
        const float* __restrict__ gW1, const float* __restrict__ gb1,
        const float* __restrict__ gW2, const float* __restrict__ gb2,
        const float* __restrict__ fW1, const float* __restrict__ fb1,
        const float* __restrict__ fW2, const float* __restrict__ fb2,
        float* __restrict__ out){
    if (blockIdx.x == 0 && threadIdx.x == 0) d_barrA = 0u;   // reset csr barrier for next call
    stage_phase(0, bn0g, bn0b, bpw + 0*512, 0.7f, 0);
    gbar(&d_barrB, 1*NBLK);
    headconv_phase(0, bWrel, bWroot, bb);
    gbar(&d_barrB, 2*NBLK);
    stage_phase(1, bbng, bbnb, bpw + 1*512, 0.7f, 1);
    gbar(&d_barrB, 3*NBLK);
    headconv_phase(1, bWrel + 4*32*EMB, bWroot + 4*32*EMB, bb + 128);
    gbar(&d_barrB, 4*NBLK);
    stage_phase(2, bbng + EMB, bbnb + EMB, cpw, 0.8f, 1);
    gbar(&d_barrB, 5*NBLK);
    cls_phase(gW1, gb1, gW2, gb2, fW1, fb1, fW2, fb2, out);
}

extern "C" void kernel_launch(void* const* d_in, const int* in_sizes, int n_in,
                              void* d_out, int out_size){
    (void)in_sizes; (void)n_in; (void)out_size;
    const float* x      = (const float*)d_in[0];
    const int*   ei     = (const int*)  d_in[1];
    const int*   src    = ei;
    const int*   dst    = ei + EDG;
    const float* Wrel0  = (const float*)d_in[3];
    const float* Wroot0 = (const float*)d_in[4];
    const float* b0     = (const float*)d_in[5];
    const float* bn0g   = (const float*)d_in[6];
    const float* bn0b   = (const float*)d_in[7];
    const float* bpw    = (const float*)d_in[8];
    const float* bWrel  = (const float*)d_in[9];
    const float* bWroot = (const float*)d_in[10];
    const float* bb     = (const float*)d_in[11];
    const float* bbng   = (const float*)d_in[12];
    const float* bbnb   = (const float*)d_in[13];
    const float* cpw    = (const float*)d_in[14];
    const float* gW1    = (const float*)d_in[15];
    const float* gb1    = (const float*)d_in[16];
    const float* gW2    = (const float*)d_in[17];
    const float* gb2    = (const float*)d_in[18];
    const float* fW1    = (const float*)d_in[19];
    const float* fb1    = (const float*)d_in[20];
    const float* fW2    = (const float*)d_in[21];
    const float* fb2    = (const float*)d_in[22];
    float* out = (float*)d_out;

    cudaFuncSetAttribute(k_gemm0, cudaFuncAttributeMaxDynamicSharedMemorySize, GSMEM);

    k_csr<<<NBLK, 256>>>(src, dst);                          // launch 0
    k_agg0<<<NN/8, 256>>>(x);                                // launch 1
    k_gemm0<<<NN/128, 256, GSMEM>>>(Wrel0, Wroot0, b0, x);   // launch 2
    k_mega<<<NBLK, 256>>>(bn0g, bn0b, bpw, bWrel, bWroot, bb, bbng, bbnb,
                          cpw, gW1, gb1, gW2, gb2, fW1, fb1, fW2, fb2, out);  // launch 3 <- profiled
}

// round 11
// speedup vs baseline: 1.5827x; 1.5368x over previous
#include <cuda_runtime.h>

#define NN   65536
#define EDG  524288
#define NPG  256
#define EMB  128
#define SLOPE 0.01f
#define NBLK 256

__device__ float d_cur[NN*EMB];
__device__ float d_agg[NN*64];
__device__ float d_hout[4*NN*32];
__device__ int   d_row[NN+1];
__device__ int   d_cnt[NN];
__device__ int   d_cursor[NN];
__device__ int   d_csrc[EDG];
__device__ int   d_bsum[256];
__device__ float d_cs1[3*128];
__device__ float d_cs2[3*128];
__device__ int   d_kc[12];
__device__ int   d_keptA[3*4*NN];
__device__ float d_smvA[3*NN*4];
__device__ unsigned char d_maskA[3*NN];
__device__ unsigned int d_barrA;
__device__ unsigned int d_barrB;
// transposed weights (filled by k_csr each call)
__device__ float d_gW1T[4*128*128];   // [c][k][o]
__device__ float d_fW1T[4*128*128];   // [c][k][o]
__device__ float d_WrelT[8*128*32];   // [stage*4+h][k][oc]
__device__ float d_WrootT[8*128*32];  // [stage*4+h][k][oc]

__device__ __forceinline__ float lrelu(float v){ return v > 0.f ? v : SLOPE*v; }
__device__ __forceinline__ float neginf(){ return __int_as_float(0xff800000); }
__device__ __forceinline__ void ffma2(unsigned long long &d, unsigned long long a, unsigned long long b){
    asm("fma.rn.f32x2 %0, %1, %2, %0;" : "+l"(d) : "l"(a), "l"(b));
}

__device__ __forceinline__ void gbar(unsigned int* ctr, unsigned int target){
    __syncthreads();
    if (threadIdx.x == 0){
        __threadfence();
        atomicAdd(ctr, 1u);
        while (*(volatile unsigned int*)ctr < target) __nanosleep(64);
        __threadfence();
    }
    __syncthreads();
}

// ================= CSR build + weight transpose, ONE persistent kernel =================
__global__ void __launch_bounds__(256,2) k_csr(const int* __restrict__ src, const int* __restrict__ dst,
        const float* __restrict__ gW1, const float* __restrict__ fW1,
        const float* __restrict__ bWrel, const float* __restrict__ bWroot){
    __shared__ int s[256];
    __shared__ int pre[256];
    __shared__ float ts[32*129];
    int t = threadIdx.x, b = blockIdx.x;
    if (b == 0 && t == 0) d_barrB = 0u;
    int e0 = b*2048;
    // phase 0a: histogram
    #pragma unroll
    for (int i = 0; i < 8; i++){
        int e = e0 + i*256 + t;
        atomicAdd(&d_cnt[dst[e]], 1);
    }
    // phase 0b: weight transposes (blocks 0..47, one 32x128 slab each)
    if (b < 48){
        const float* in; float* outp; int ocols, o0;
        if (b < 16){       int c = b >> 2; o0 = (b & 3)*32; in = gW1 + c*16384; outp = d_gW1T + c*16384; ocols = 128; }
        else if (b < 32){  int c = (b-16) >> 2; o0 = (b & 3)*32; in = fW1 + c*16384; outp = d_fW1T + c*16384; ocols = 128; }
        else if (b < 40){  int m = b-32; o0 = 0; in = bWrel + m*4096; outp = d_WrelT + m*4096; ocols = 32; }
        else {             int m = b-40; o0 = 0; in = bWroot + m*4096; outp = d_WrootT + m*4096; ocols = 32; }
        for (int i = t; i < 4096; i += 256){
            int r = i >> 7, k = i & 127;
            ts[r*129 + k] = in[(o0 + r)*128 + k];
        }
        __syncthreads();
        for (int i = t; i < 4096; i += 256){
            int k = i >> 5, ol = i & 31;
            outp[k*ocols + o0 + ol] = ts[ol*129 + k];
        }
    }
    gbar(&d_barrA, 1*NBLK);
    // phase 1: per-block scan
    int gid = b*256 + t;
    int v = __ldcg(&d_cnt[gid]);
    d_cnt[gid] = 0;
    s[t] = v; __syncthreads();
    for (int off = 1; off < 256; off <<= 1){
        int u = (t >= off) ? s[t-off] : 0;
        __syncthreads();
        s[t] += u; __syncthreads();
    }
    d_row[gid] = s[t] - v;
    if (t == 255) d_bsum[b] = s[255];
    gbar(&d_barrA, 2*NBLK);
    // phase 2: global offsets + init
    pre[t] = (t < b) ? __ldcg(&d_bsum[t]) : 0;
    __syncthreads();
    for (int off = 128; off; off >>= 1){
        if (t < off) pre[t] += pre[t+off];
        __syncthreads();
    }
    int r = pre[0] + d_row[gid];
    d_row[gid] = r;
    d_cursor[gid] = r;
    if (gid == NN-1) d_row[NN] = EDG;
    if (b == 0){
        if (t < 128){
            #pragma unroll
            for (int st = 0; st < 3; st++){ d_cs1[st*128+t] = 0.f; d_cs2[st*128+t] = 0.f; }
        }
        if (t < 12) d_kc[t] = 0;
    }
    gbar(&d_barrA, 3*NBLK);
    // phase 3: fill
    #pragma unroll
    for (int i = 0; i < 8; i++){
        int e = e0 + i*256 + t;
        int d = dst[e];
        int p = atomicAdd(&d_cursor[d], 1);
        d_csrc[p] = src[e];
    }
}

// ---------------- conv0 segment-max (warp per node) ----------------
__global__ void k_agg0(const float* __restrict__ x){
    int wid  = (blockIdx.x*blockDim.x + threadIdx.x) >> 5;
    int lane = threadIdx.x & 31;
    int beg = d_row[wid], end = d_row[wid+1];
    float2 m = make_float2(neginf(), neginf());
    for (int base = beg; base < end; base += 32){
        int j = base + lane;
        int s = (j < end) ? d_csrc[j] : 0;
        int c = min(32, end - base);
        for (int t = 0; t < c; t++){
            int ss = __shfl_sync(0xffffffffu, s, t);
            float2 v = *(const float2*)(x + ss*64 + lane*2);
            m.x = fmaxf(m.x, v.x); m.y = fmaxf(m.y, v.y);
        }
    }
    if (m.x == neginf()) m.x = 0.f;
    if (m.y == neginf()) m.y = 0.f;
    *(float2*)(d_agg + wid*64 + lane*2) = m;
}

// ---------------- conv0 GEMM (128x128 tile, 8x8/thread, FFMA2) ----------------
#define GSMEM (2*128*132*4 + 256*4)
__global__ void __launch_bounds__(256,1) k_gemm0(const float* __restrict__ Wrel,
        const float* __restrict__ Wroot, const float* __restrict__ bias,
        const float* __restrict__ x){
    extern __shared__ float smp[];
    float* As  = smp;
    float* Ws  = smp + 128*132;
    float* sc1 = smp + 2*128*132;
    float* sc2 = sc1 + 128;
    int tid = threadIdx.x;
    int row0 = blockIdx.x*128;
    for (int idx = tid; idx < 128*128; idx += 256){
        int r = idx >> 7, c = idx & 127;
        As[r*132+c] = (c < 64) ? d_agg[(row0+r)*64 + c] : x[(row0+r)*64 + (c-64)];
        Ws[r*132+c] = (c < 64) ? Wrel[r*64 + c] : Wroot[r*64 + (c-64)];
    }
    if (tid < 128){ sc1[tid] = 0.f; sc2[tid] = 0.f; }
    __syncthreads();
    int tx = tid & 15, ty = tid >> 4;
    unsigned long long acc[8][8];
    #pragma unroll
    for (int r = 0; r < 8; r++)
        #pragma unroll
        for (int c = 0; c < 8; c++) acc[r][c] = 0ull;
    int ra = ty*4, rb = 64 + ty*4;
    for (int k = 0; k < 128; k += 4){
        ulonglong2 a[8];
        #pragma unroll
        for (int r = 0; r < 4; r++){
            a[r]   = *(const ulonglong2*)(As + (ra+r)*132 + k);
            a[r+4] = *(const ulonglong2*)(As + (rb+r)*132 + k);
        }
        #pragma unroll
        for (int cc = 0; cc < 8; cc++){
            ulonglong2 w = *(const ulonglong2*)(Ws + (cc*16+tx)*132 + k);
            #pragma unroll
            for (int r = 0; r < 8; r++){
                ffma2(acc[r][cc], a[r].x, w.x);
                ffma2(acc[r][cc], a[r].y, w.y);
            }
        }
    }
    #pragma unroll
    for (int cc = 0; cc < 8; cc++){
        int col = cc*16 + tx;
        float b = __ldg(&bias[col]);
        float a1 = 0.f, a2 = 0.f;
        #pragma unroll
        for (int r = 0; r < 8; r++){
            float2 f = *(float2*)&acc[r][cc];
            float h = f.x + f.y + b;
            h = (h > 0.f) ? h : SLOPE*h;
            int row = row0 + ((r < 4) ? (ra+r) : (rb+r-4));
            d_cur[row*EMB + col] = h;
            a1 += h; a2 += h*h;
        }
        atomicAdd(&sc1[col], a1);
        atomicAdd(&sc2[col], a2);
    }
    __syncthreads();
    if (tid < 128){
        atomicAdd(&d_cs1[tid], sc1[tid]);
        atomicAdd(&d_cs2[tid], sc2[tid]);
    }
}

// ================= persistent mega kernel =================
__device__ void stage_phase(int stage, const float* __restrict__ bng, const float* __restrict__ bnb,
                            const float* __restrict__ w4, float min_score, int mode){
    __shared__ float sscale[128], sshift[128], scorr[128], sw[512];
    __shared__ float sc0[256], sc1v[256], sc2v[256], sc3v[256];
    __shared__ float4 red[256];
    __shared__ float sm4[4], ssum[4], sthr[4];
    int t = threadIdx.x, g = blockIdx.x;
    if (t < 128){
        float c1 = __ldcg(&d_cs1[stage*128 + t]);
        float c2 = __ldcg(&d_cs2[stage*128 + t]);
        float mu  = c1 * (1.f/NN);
        float var = c2 * (1.f/NN) - mu*mu;
        float r   = rsqrtf(var + 1e-5f);
        float gr  = bng[t]*r;
        if (mode == 0){ sscale[t] = gr;   sshift[t] = bnb[t] - gr*mu;          scorr[t] = 0.f; }
        else          { sscale[t] = 0.5f; sshift[t] = 0.25f*(bnb[t] - gr*mu);  scorr[t] = 0.25f*gr; }
    }
    sw[t] = w4[t]; sw[t+256] = w4[t+256];
    __syncthreads();
    int w = t >> 5, lane = t & 31;
    int hd = lane >> 3;
    float4 scv = *(float4*)(sscale + lane*4);
    float4 shv = *(float4*)(sshift + lane*4);
    float4 crv = *(float4*)(scorr + lane*4);
    float4 wv0 = *(float4*)(sw + lane*4);
    float4 wv1 = *(float4*)(sw + 128 + lane*4);
    float4 wv2 = *(float4*)(sw + 256 + lane*4);
    float4 wv3 = *(float4*)(sw + 384 + lane*4);
    const unsigned char* pmv = d_maskA + (stage > 0 ? (stage-1) : 0)*NN;
    #pragma unroll 1
    for (int it = 0; it < 32; it++){
        int idx = it*8 + w;
        int n = g*NPG + idx;
        float4 v = *(float4*)(d_cur + n*EMB + lane*4);
        v.x = scv.x*v.x + shv.x; v.y = scv.y*v.y + shv.y;
        v.z = scv.z*v.z + shv.z; v.w = scv.w*v.w + shv.w;
        if (mode){
            unsigned char pm = __ldcg(&pmv[n]);
            if ((pm >> hd) & 1){
                float4 o = __ldcg((const float4*)(d_hout + (hd*NN + n)*32 + (lane & 7)*4));
                v.x += crv.x*o.x; v.y += crv.y*o.y; v.z += crv.z*o.z; v.w += crv.w*o.w;
            }
        }
        *(float4*)(d_cur + n*EMB + lane*4) = v;
        float p0 = v.x*wv0.x + v.y*wv0.y + v.z*wv0.z + v.w*wv0.w;
        float p1 = v.x*wv1.x + v.y*wv1.y + v.z*wv1.z + v.w*wv1.w;
        float p2 = v.x*wv2.x + v.y*wv2.y + v.z*wv2.z + v.w*wv2.w;
        float p3 = v.x*wv3.x + v.y*wv3.y + v.z*wv3.z + v.w*wv3.w;
        #pragma unroll
        for (int off = 16; off; off >>= 1){
            p0 += __shfl_xor_sync(0xffffffffu, p0, off);
            p1 += __shfl_xor_sync(0xffffffffu, p1, off);
            p2 += __shfl_xor_sync(0xffffffffu, p2, off);
            p3 += __shfl_xor_sync(0xffffffffu, p3, off);
        }
        if (lane == 0){ sc0[idx] = p0; sc1v[idx] = p1; sc2v[idx] = p2; sc3v[idx] = p3; }
    }
    __syncthreads();
    float4 z = make_float4(sc0[t], sc1v[t], sc2v[t], sc3v[t]);
    red[t] = z; __syncthreads();
    for (int off = 128; off; off >>= 1){
        if (t < off){
            float4 a = red[t], b = red[t+off];
            red[t] = make_float4(fmaxf(a.x,b.x), fmaxf(a.y,b.y), fmaxf(a.z,b.z), fmaxf(a.w,b.w));
        }
        __syncthreads();
    }
    if (t == 0){ float4 mm = red[0]; sm4[0]=mm.x; sm4[1]=mm.y; sm4[2]=mm.z; sm4[3]=mm.w; }
    __syncthreads();
    float4 e = make_float4(expf(z.x-sm4[0]), expf(z.y-sm4[1]), expf(z.z-sm4[2]), expf(z.w-sm4[3]));
    red[t] = e; __syncthreads();
    for (int off = 128; off; off >>= 1){
        if (t < off){
            float4 a = red[t], b = red[t+off];
            red[t] = make_float4(a.x+b.x, a.y+b.y, a.z+b.z, a.w+b.w);
        }
        __syncthreads();
    }
    if (t == 0){ float4 ss = red[0]; ssum[0]=ss.x; ssum[1]=ss.y; ssum[2]=ss.z; ssum[3]=ss.w; }
    __syncthreads();
    if (t < 4) sthr[t] = fminf(1.f/(ssum[t] + 1e-16f) - 1e-7f, min_score);
    __syncthreads();
    int n = g*NPG + t;
    float sv0 = e.x/(ssum[0]+1e-16f), sv1 = e.y/(ssum[1]+1e-16f);
    float sv2 = e.z/(ssum[2]+1e-16f), sv3 = e.w/(ssum[3]+1e-16f);
    int* kc = d_kc + stage*4;
    int* kept = d_keptA + stage*4*NN;
    unsigned char mk = 0;
    if (sv0 > sthr[0]){ mk |= 1; kept[0*NN + atomicAdd(kc+0,1)] = n; }
    if (sv1 > sthr[1]){ mk |= 2; kept[1*NN + atomicAdd(kc+1,1)] = n; }
    if (sv2 > sthr[2]){ mk |= 4; kept[2*NN + atomicAdd(kc+2,1)] = n; }
    if (sv3 > sthr[3]){ mk |= 8; kept[3*NN + atomicAdd(kc+3,1)] = n; }
    *(float4*)(d_smvA + (stage*NN + n)*4) = make_float4(sv0, sv1, sv2, sv3);
    d_maskA[stage*NN + n] = mk;
}

__device__ void headconv_phase(int stage, const float* __restrict__ bias){
    __shared__ float hax[128], hxs[128], hred[256];
    int t = threadIdx.x;
    int oc = t & 31, q = t >> 5;
    const unsigned char* mv = d_maskA + stage*NN;
    const float* sv = d_smvA + stage*NN*4;
    float* cs1 = d_cs1 + (stage+1)*128;
    float* cs2 = d_cs2 + (stage+1)*128;
    #pragma unroll 1
    for (int h = 0; h < 4; h++){
        int nk = __ldcg(&d_kc[stage*4 + h]);
        unsigned char bit = (unsigned char)(1 << h);
        const int* kept = d_keptA + (stage*4 + h)*NN;
        const float* wrT = d_WrelT  + (stage*4 + h)*4096;   // [k][oc]
        const float* wtT = d_WrootT + (stage*4 + h)*4096;
        for (int slot = blockIdx.x; slot < nk; slot += NBLK){
            int i = __ldcg(&kept[slot]);
            if (t < 128){
                float m = neginf();
                int beg = d_row[i], end = d_row[i+1];
                for (int j = beg; j < end; j++){
                    int s = d_csrc[j];
                    if (__ldcg(&mv[s]) & bit)
                        m = fmaxf(m, __ldcg(&d_cur[s*EMB + t]) * __ldcg(&sv[s*4 + h]));
                }
                hax[t] = (m == neginf()) ? 0.f : m;
                hxs[t] = __ldcg(&d_cur[i*EMB + t]) * __ldcg(&sv[i*4 + h]);
            }
            __syncthreads();
            {
                float acc = 0.f;
                #pragma unroll
                for (int k = 0; k < 16; k++){
                    int kk = q*16 + k;
                    acc += hax[kk]*wrT[kk*32 + oc] + hxs[kk]*wtT[kk*32 + oc];
                }
                hred[t] = acc;
            }
            __syncthreads();
            if (q == 0){
                float o = bias[h*32 + oc];
                #pragma unroll
                for (int p = 0; p < 8; p++) o += hred[p*32 + oc];
                o = lrelu(o);
                d_hout[(h*NN + i)*32 + oc] = o;
                atomicAdd(&cs1[h*32 + oc], o);
                atomicAdd(&cs2[h*32 + oc], o*o);
            }
            __syncthreads();
        }
    }
}

__device__ void cls_phase(const float* __restrict__ gb1,
                          const float* __restrict__ gW2, const float* __restrict__ gb2,
                          const float* __restrict__ fb1,
                          const float* __restrict__ fW2, const float* __restrict__ fb2,
                          float* __restrict__ out){
    __shared__ float cxp[128], cpool[128], cred[256], cgates[16], cslog[4];
    __shared__ int cknod[16], ckn;
    int g = blockIdx.x, t = threadIdx.x;
    int o = t & 127, half = t >> 7;       // 2-way k-split
    const unsigned char* mv = d_maskA + 2*NN;
    const float* sv = d_smvA + 2*NN*4;
    #pragma unroll 1
    for (int c = 0; c < 4; c++){
        if (t == 0) ckn = 0;
        __syncthreads();
        {
            int n = g*NPG + t;
            if ((mv[n] >> c) & 1){
                int idx = atomicAdd(&ckn, 1);
                if (idx < 16) cknod[idx] = n;
            }
        }
        __syncthreads();
        int K = min(ckn, 16);
        const float* gT = d_gW1T + c*16384;
        const float* fT = d_fW1T + c*16384;
        for (int ki = 0; ki < K; ki++){
            int i = cknod[ki];
            if (t < 128) cxp[t] = d_cur[i*EMB + t] * sv[i*4 + c];
            __syncthreads();
            {
                float acc = 0.f;
                #pragma unroll 8
                for (int k = 0; k < 64; k++){
                    int kk = half*64 + k;
                    acc += cxp[kk]*gT[kk*128 + o];
                }
                cred[t] = acc;
            }
            __syncthreads();
            if (t < 128) cred[t] = lrelu(cred[t] + cred[t+128] + gb1[c*128 + t]) * gW2[c*128 + t];
            __syncthreads();
            for (int off = 64; off; off >>= 1){
                if (t < off) cred[t] += cred[t+off];
                __syncthreads();
            }
            if (t == 0) cgates[ki] = cred[0] + gb2[c];
            __syncthreads();
        }
        float m = neginf();
        for (int ki = 0; ki < K; ki++) m = fmaxf(m, cgates[ki]);
        float s = 0.f;
        for (int ki = 0; ki < K; ki++) s += expf(cgates[ki] - m);
        float inv = 1.f/(s + 1e-16f);
        if (t < 128){
            float p = 0.f;
            for (int ki = 0; ki < K; ki++){
                int i = cknod[ki];
                float aw = expf(cgates[ki] - m) * inv * sv[i*4 + c];
                p += aw * d_cur[i*EMB + t];
            }
            cpool[t] = p;
        }
        __syncthreads();
        {
            float acc = 0.f;
            #pragma unroll 8
            for (int k = 0; k < 64; k++){
                int kk = half*64 + k;
                acc += cpool[kk]*fT[kk*128 + o];
            }
            cred[t] = acc;
        }
        __syncthreads();
        if (t < 128) cred[t] = lrelu(cred[t] + cred[t+128] + fb1[c*128 + t]) * fW2[c*128 + t];
        __syncthreads();
        for (int off = 64; off; off >>= 1){
            if (t < off) cred[t] += cred[t+off];
            __syncthreads();
        }
        if (t == 0) cslog[c] = cred[0] + fb2[c];
        __syncthreads();
    }
    if (t == 0){
        float z0 = cslog[0], z1 = cslog[1], z2 = cslog[2], z3 = cslog[3];
        float m = fmaxf(fmaxf(z0,z1), fmaxf(z2,z3));
        float l = logf(expf(z0-m) + expf(z1-m) + expf(z2-m) + expf(z3-m));
        out[g*4+0] = z0 - m - l;
        out[g*4+1] = z1 - m - l;
        out[g*4+2] = z2 - m - l;
        out[g*4+3] = z3 - m - l;
    }
}

__global__ void __launch_bounds__(256,2) k_mega(
        const float* __restrict__ bn0g, const float* __restrict__ bn0b,
        const float* __restrict__ bpw,
        const float* __restrict__ bb,
        const float* __restrict__ bbng, const float* __restrict__ bbnb,
        const float* __restrict__ cpw,
        const float* __restrict__ gb1,
        const float* __restrict__ gW2, const float* __restrict__ gb2,
        const float* __restrict__ fb1,
        const float* __restrict__ fW2, const float* __restrict__ fb2,
        float* __restrict__ out){
    if (blockIdx.x == 0 && threadIdx.x == 0) d_barrA = 0u;
    stage_phase(0, bn0g, bn0b, bpw + 0*512, 0.7f, 0);
    gbar(&d_barrB, 1*NBLK);
    headconv_phase(0, bb);
    gbar(&d_barrB, 2*NBLK);
    stage_phase(1, bbng, bbnb, bpw + 1*512, 0.7f, 1);
    gbar(&d_barrB, 3*NBLK);
    headconv_phase(1, bb + 128);
    gbar(&d_barrB, 4*NBLK);
    stage_phase(2, bbng + EMB, bbnb + EMB, cpw, 0.8f, 1);
    gbar(&d_barrB, 5*NBLK);
    cls_phase(gb1, gW2, gb2, fb1, fW2, fb2, out);
}

extern "C" void kernel_launch(void* const* d_in, const int* in_sizes, int n_in,
                              void* d_out, int out_size){
    (void)in_sizes; (void)n_in; (void)out_size;
    const float* x      = (const float*)d_in[0];
    const int*   ei     = (const int*)  d_in[1];
    const int*   src    = ei;
    const int*   dst    = ei + EDG;
    const float* Wrel0  = (const float*)d_in[3];
    const float* Wroot0 = (const float*)d_in[4];
    const float* b0     = (const float*)d_in[5];
    const float* bn0g   = (const float*)d_in[6];
    const float* bn0b   = (const float*)d_in[7];
    const float* bpw    = (const float*)d_in[8];
    const float* bWrel  = (const float*)d_in[9];
    const float* bWroot = (const float*)d_in[10];
    const float* bb     = (const float*)d_in[11];
    const float* bbng   = (const float*)d_in[12];
    const float* bbnb   = (const float*)d_in[13];
    const float* cpw    = (const float*)d_in[14];
    const float* gW1    = (const float*)d_in[15];
    const float* gb1    = (const float*)d_in[16];
    const float* gW2    = (const float*)d_in[17];
    const float* gb2    = (const float*)d_in[18];
    const float* fW1    = (const float*)d_in[19];
    const float* fb1    = (const float*)d_in[20];
    const float* fW2    = (const float*)d_in[21];
    const float* fb2    = (const float*)d_in[22];
    float* out = (float*)d_out;

    cudaFuncSetAttribute(k_gemm0, cudaFuncAttributeMaxDynamicSharedMemorySize, GSMEM);

    k_csr<<<NBLK, 256>>>(src, dst, gW1, fW1, bWrel, bWroot);  // launch 0
    k_agg0<<<NN/8, 256>>>(x);                                 // launch 1
    k_gemm0<<<NN/128, 256, GSMEM>>>(Wrel0, Wroot0, b0, x);    // launch 2
    k_mega<<<NBLK, 256>>>(bn0g, bn0b, bpw, bb, bbng, bbnb, cpw,
                          gb1, gW2, gb2, fb1, fW2, fb2, out); // launch 3 <- profiled
}